// round 4
// baseline (speedup 1.0000x reference)
#include <cuda_runtime.h>

#define NN 50000
#define EE 800000
#define HH 128

// Scratch (device globals: no allocation allowed)
__device__ float g_summed[NN * HH];
__device__ float g_counts[NN];
__device__ float g_px[NN * HH];
__device__ int   g_idx64;

__device__ __forceinline__ int get_idx(const void* p, long long i) {
    return g_idx64 ? (int)((const long long*)p)[i] : ((const int*)p)[i];
}

// ---- packed f32x2 helpers (B300: FFMA-3reg is half-rate; f32x2 restores peak)
__device__ __forceinline__ unsigned long long pack2(float x, float y) {
    unsigned long long r;
    asm("mov.b64 %0, {%1, %2};" : "=l"(r) : "f"(x), "f"(y));
    return r;
}
__device__ __forceinline__ unsigned long long dup2(float x) {
    unsigned long long r;
    asm("mov.b64 %0, {%1, %1};" : "=l"(r) : "f"(x));
    return r;
}
__device__ __forceinline__ void unpack2(unsigned long long p, float& lo, float& hi) {
    asm("mov.b64 {%0, %1}, %2;" : "=f"(lo), "=f"(hi) : "l"(p));
}
__device__ __forceinline__ void ffma2(unsigned long long& d,
                                      unsigned long long a, unsigned long long b) {
    asm("fma.rn.f32x2 %0, %1, %2, %0;" : "+l"(d) : "l"(a), "l"(b));
}

// swizzled k-major tile addressing: 128 words per row, 4-float chunk XOR swizzle
__device__ __forceinline__ int tidx(int k, int m) {
    return k * 128 + ((((m >> 2) ^ ((k >> 2) & 31)) << 2) | (m & 3));
}

__global__ void detect_kernel(const int* __restrict__ idx32) {
    if (blockIdx.x == 0 && threadIdx.x == 0) {
        int is64 = 1;
        #pragma unroll 1
        for (int i = 0; i < 64; ++i) {
            if (idx32[2 * i + 1] != 0) { is64 = 0; break; }
        }
        g_idx64 = is64;
    }
}

__global__ void zero_kernel() {
    int stride = gridDim.x * blockDim.x;
    int t0 = blockIdx.x * blockDim.x + threadIdx.x;
    for (int j = t0; j < NN * HH; j += stride) g_summed[j] = 0.f;
    for (int j = t0; j < NN; j += stride) g_counts[j] = 0.f;
}

// 128x128x128 GEMM inner: As swizzled k-major, Ws plain row-major [k][n].
// Thread (tm,tn) covers rows 8*tm..8*tm+7, cols {4*tn..+3} u {64+4*tn..+3}.
__device__ __forceinline__ void gemm_tile(const float* __restrict__ As,
                                          const float* __restrict__ Ws,
                                          int tm, int tn,
                                          unsigned long long accp[8][4]) {
    #pragma unroll 2
    for (int k = 0; k < 128; k++) {
        int xk = (k >> 2) & 31;
        float4 a0 = *(const float4*)(As + k * 128 + (((2 * tm)     ^ xk) << 2));
        float4 a1 = *(const float4*)(As + k * 128 + (((2 * tm + 1) ^ xk) << 2));
        float4 b0 = *(const float4*)(Ws + k * 128 + 4 * tn);
        float4 b1 = *(const float4*)(Ws + k * 128 + 64 + 4 * tn);
        unsigned long long bp0 = pack2(b0.x, b0.y);
        unsigned long long bp1 = pack2(b0.z, b0.w);
        unsigned long long bp2 = pack2(b1.x, b1.y);
        unsigned long long bp3 = pack2(b1.z, b1.w);
        float a[8] = {a0.x, a0.y, a0.z, a0.w, a1.x, a1.y, a1.z, a1.w};
        #pragma unroll
        for (int i = 0; i < 8; i++) {
            unsigned long long ad = dup2(a[i]);
            ffma2(accp[i][0], ad, bp0);
            ffma2(accp[i][1], ad, bp1);
            ffma2(accp[i][2], ad, bp2);
            ffma2(accp[i][3], ad, bp3);
        }
    }
}

// ---------------------------------------------------------------------------
// px = x @ W1a[0:128,:] + b1a   (kept from round 1; small share of runtime)
// ---------------------------------------------------------------------------
__global__ void px_kernel(const float* __restrict__ x,
                          const float* __restrict__ W1a,
                          const float* __restrict__ b1a) {
    extern __shared__ float sm[];
    float* As = sm;              // [128][65] k-major A tile
    float* Ws = sm + 128 * 65;   // [128][128]

    const int tid = threadIdx.x;
    const int tm = tid >> 4, tn = tid & 15;
    const int warp = tid >> 5, lane = tid & 31;
    const int m0 = blockIdx.x * 64;

    for (int r = warp; r < 64; r += 8) {
        int gm = m0 + r;
        float4 v = make_float4(0.f, 0.f, 0.f, 0.f);
        if (gm < NN) v = *(const float4*)(x + (size_t)gm * HH + lane * 4);
        int k = lane * 4;
        As[(k + 0) * 65 + r] = v.x;
        As[(k + 1) * 65 + r] = v.y;
        As[(k + 2) * 65 + r] = v.z;
        As[(k + 3) * 65 + r] = v.w;
    }
    for (int i = tid * 4; i < 128 * 128; i += 1024)
        *(float4*)(Ws + i) = *(const float4*)(W1a + i);
    __syncthreads();

    float acc[4][8];
    #pragma unroll
    for (int i = 0; i < 4; i++)
        #pragma unroll
        for (int j = 0; j < 8; j++) acc[i][j] = 0.f;

    #pragma unroll 4
    for (int k = 0; k < 128; k++) {
        float a[4], b[8];
        #pragma unroll
        for (int i = 0; i < 4; i++) a[i] = As[k * 65 + 4 * tm + i];
        float4 b0 = *(float4*)(Ws + k * 128 + 8 * tn);
        float4 b1 = *(float4*)(Ws + k * 128 + 8 * tn + 4);
        b[0] = b0.x; b[1] = b0.y; b[2] = b0.z; b[3] = b0.w;
        b[4] = b1.x; b[5] = b1.y; b[6] = b1.z; b[7] = b1.w;
        #pragma unroll
        for (int i = 0; i < 4; i++)
            #pragma unroll
            for (int j = 0; j < 8; j++) acc[i][j] += a[i] * b[j];
    }

    float bv[8];
    #pragma unroll
    for (int j = 0; j < 8; j++) bv[j] = b1a[8 * tn + j];
    #pragma unroll
    for (int i = 0; i < 4; i++) {
        int m = m0 + 4 * tm + i;
        if (m < NN) {
            float4 o0 = make_float4(acc[i][0] + bv[0], acc[i][1] + bv[1],
                                    acc[i][2] + bv[2], acc[i][3] + bv[3]);
            float4 o1 = make_float4(acc[i][4] + bv[4], acc[i][5] + bv[5],
                                    acc[i][6] + bv[6], acc[i][7] + bv[7]);
            *(float4*)(g_px + (size_t)m * HH + 8 * tn) = o0;
            *(float4*)(g_px + (size_t)m * HH + 8 * tn + 4) = o1;
        }
    }
}

// ---------------------------------------------------------------------------
// Edge kernel: 128-edge tiles, f32x2 GEMMs, LN, atomic scatter
// ---------------------------------------------------------------------------
__global__ __launch_bounds__(256, 1)
void edge_kernel(const float* __restrict__ edge_attr,
                 const void* __restrict__ eidx,
                 const float* __restrict__ W1a,
                 const float* __restrict__ W2a,
                 const float* __restrict__ b2a,
                 const float* __restrict__ g1,
                 const float* __restrict__ be1) {
    extern __shared__ float sm[];
    float* As = sm;              // swizzled k-major [128][128]
    float* Ws = sm + 128 * 128;  // [128][128]
    __shared__ int s_rows[128];
    __shared__ int s_cols[128];

    const int tid = threadIdx.x;
    const int tm = tid >> 4, tn = tid & 15;
    const int warp = tid >> 5, lane = tid & 31;
    const long long e0 = (long long)blockIdx.x * 128;

    if (tid < 128) {
        s_rows[tid] = get_idx(eidx, e0 + tid);
        s_cols[tid] = get_idx(eidx, (long long)EE + e0 + tid);
    }
    // edge_attr tile -> swizzled k-major
    for (int r = warp; r < 128; r += 8) {
        float4 v = *(const float4*)(edge_attr + (size_t)(e0 + r) * HH + 4 * lane);
        int k0 = 4 * lane;
        As[tidx(k0 + 0, r)] = v.x;
        As[tidx(k0 + 1, r)] = v.y;
        As[tidx(k0 + 2, r)] = v.z;
        As[tidx(k0 + 3, r)] = v.w;
    }
    const float* W1e = W1a + 128 * 128;
    for (int i = tid * 4; i < 128 * 128; i += 1024)
        *(float4*)(Ws + i) = *(const float4*)(W1e + i);
    __syncthreads();

    unsigned long long accp[8][4];
    #pragma unroll
    for (int i = 0; i < 8; i++)
        #pragma unroll
        for (int j = 0; j < 4; j++) accp[i][j] = 0ULL;

    gemm_tile(As, Ws, tm, tn, accp);

    // h = relu(acc + px[col])
    float h[8][8];
    #pragma unroll
    for (int i = 0; i < 8; i++) {
        #pragma unroll
        for (int jp = 0; jp < 4; jp++)
            unpack2(accp[i][jp], h[i][2 * jp], h[i][2 * jp + 1]);
        int c = s_cols[8 * tm + i];
        float4 p0 = *(const float4*)(g_px + (size_t)c * HH + 4 * tn);
        float4 p1 = *(const float4*)(g_px + (size_t)c * HH + 64 + 4 * tn);
        h[i][0] = fmaxf(h[i][0] + p0.x, 0.f);
        h[i][1] = fmaxf(h[i][1] + p0.y, 0.f);
        h[i][2] = fmaxf(h[i][2] + p0.z, 0.f);
        h[i][3] = fmaxf(h[i][3] + p0.w, 0.f);
        h[i][4] = fmaxf(h[i][4] + p1.x, 0.f);
        h[i][5] = fmaxf(h[i][5] + p1.y, 0.f);
        h[i][6] = fmaxf(h[i][6] + p1.z, 0.f);
        h[i][7] = fmaxf(h[i][7] + p1.w, 0.f);
    }
    __syncthreads();   // all GEMM1 reads of As/Ws complete

    // store h -> As (k-major over n), load W2a -> Ws
    #pragma unroll
    for (int j = 0; j < 8; j++) {
        int n = (j < 4) ? (4 * tn + j) : (64 + 4 * tn + j - 4);
        int xk = (n >> 2) & 31;
        float4 c0 = make_float4(h[0][j], h[1][j], h[2][j], h[3][j]);
        float4 c1 = make_float4(h[4][j], h[5][j], h[6][j], h[7][j]);
        *(float4*)(As + n * 128 + (((2 * tm)     ^ xk) << 2)) = c0;
        *(float4*)(As + n * 128 + (((2 * tm + 1) ^ xk) << 2)) = c1;
    }
    for (int i = tid * 4; i < 128 * 128; i += 1024)
        *(float4*)(Ws + i) = *(const float4*)(W2a + i);
    __syncthreads();

    #pragma unroll
    for (int i = 0; i < 8; i++)
        #pragma unroll
        for (int j = 0; j < 4; j++) accp[i][j] = 0ULL;

    gemm_tile(As, Ws, tm, tn, accp);

    // epilogue: bias, LayerNorm per edge-row, atomic scatter
    float y[8][8];
    float b2v[8], gv[8], bev[8];
    #pragma unroll
    for (int j = 0; j < 8; j++) {
        int col = (j < 4) ? (4 * tn + j) : (64 + 4 * tn + j - 4);
        b2v[j] = b2a[col]; gv[j] = g1[col]; bev[j] = be1[col];
    }
    #pragma unroll
    for (int i = 0; i < 8; i++) {
        #pragma unroll
        for (int jp = 0; jp < 4; jp++)
            unpack2(accp[i][jp], y[i][2 * jp], y[i][2 * jp + 1]);
        float s = 0.f, s2 = 0.f;
        #pragma unroll
        for (int j = 0; j < 8; j++) {
            y[i][j] += b2v[j];
            s += y[i][j]; s2 += y[i][j] * y[i][j];
        }
        #pragma unroll
        for (int o = 1; o < 16; o <<= 1) {
            s  += __shfl_xor_sync(0xffffffffu, s, o);
            s2 += __shfl_xor_sync(0xffffffffu, s2, o);
        }
        float mean = s * (1.f / 128.f);
        float var  = s2 * (1.f / 128.f) - mean * mean;
        float rstd = rsqrtf(var + 1e-5f);
        int r = s_rows[8 * tm + i];
        float* dst = g_summed + (size_t)r * HH;
        #pragma unroll
        for (int j = 0; j < 8; j++) {
            int col = (j < 4) ? (4 * tn + j) : (64 + 4 * tn + j - 4);
            atomicAdd(dst + col, (y[i][j] - mean) * rstd * gv[j] + bev[j]);
        }
    }
    if (tn == 0) {
        #pragma unroll
        for (int i = 0; i < 8; i++)
            atomicAdd(&g_counts[s_rows[8 * tm + i]], 1.f);
    }
}

// ---------------------------------------------------------------------------
// Node kernel: z = [x, summed/max(cnt,1), u] (128x384) in 3 segments
// ---------------------------------------------------------------------------
__global__ __launch_bounds__(256, 1)
void node_kernel(const float* __restrict__ x,
                 const float* __restrict__ u,
                 const float* __restrict__ W1b,
                 const float* __restrict__ b1b,
                 const float* __restrict__ W2b,
                 const float* __restrict__ b2b,
                 const float* __restrict__ g2,
                 const float* __restrict__ be2,
                 float* __restrict__ out) {
    extern __shared__ float sm[];
    float* As = sm;
    float* Ws = sm + 128 * 128;

    const int tid = threadIdx.x;
    const int tm = tid >> 4, tn = tid & 15;
    const int warp = tid >> 5, lane = tid & 31;
    const int m0 = blockIdx.x * 128;

    unsigned long long accp[8][4];
    #pragma unroll
    for (int i = 0; i < 8; i++)
        #pragma unroll
        for (int j = 0; j < 4; j++) accp[i][j] = 0ULL;

    for (int seg = 0; seg < 3; seg++) {
        if (seg) __syncthreads();  // prior GEMM reads done before overwrite
        for (int r = warp; r < 128; r += 8) {
            int gm = m0 + r;
            float4 v = make_float4(0.f, 0.f, 0.f, 0.f);
            if (gm < NN) {
                if (seg == 0) {
                    v = *(const float4*)(x + (size_t)gm * HH + 4 * lane);
                } else if (seg == 1) {
                    v = *(const float4*)(g_summed + (size_t)gm * HH + 4 * lane);
                    float inv = 1.f / fmaxf(g_counts[gm], 1.f);
                    v.x *= inv; v.y *= inv; v.z *= inv; v.w *= inv;
                } else {
                    v = *(const float4*)(u + (size_t)gm * HH + 4 * lane);
                }
            }
            int k0 = 4 * lane;
            As[tidx(k0 + 0, r)] = v.x;
            As[tidx(k0 + 1, r)] = v.y;
            As[tidx(k0 + 2, r)] = v.z;
            As[tidx(k0 + 3, r)] = v.w;
        }
        for (int i = tid * 4; i < 128 * 128; i += 1024)
            *(float4*)(Ws + i) = *(const float4*)(W1b + seg * 128 * 128 + i);
        __syncthreads();
        gemm_tile(As, Ws, tm, tn, accp);
    }

    // h = relu(acc + b1b)
    float h[8][8];
    float b1v[8];
    #pragma unroll
    for (int j = 0; j < 8; j++) {
        int col = (j < 4) ? (4 * tn + j) : (64 + 4 * tn + j - 4);
        b1v[j] = b1b[col];
    }
    #pragma unroll
    for (int i = 0; i < 8; i++) {
        #pragma unroll
        for (int jp = 0; jp < 4; jp++)
            unpack2(accp[i][jp], h[i][2 * jp], h[i][2 * jp + 1]);
        #pragma unroll
        for (int j = 0; j < 8; j++) h[i][j] = fmaxf(h[i][j] + b1v[j], 0.f);
    }
    __syncthreads();

    #pragma unroll
    for (int j = 0; j < 8; j++) {
        int n = (j < 4) ? (4 * tn + j) : (64 + 4 * tn + j - 4);
        int xk = (n >> 2) & 31;
        float4 c0 = make_float4(h[0][j], h[1][j], h[2][j], h[3][j]);
        float4 c1 = make_float4(h[4][j], h[5][j], h[6][j], h[7][j]);
        *(float4*)(As + n * 128 + (((2 * tm)     ^ xk) << 2)) = c0;
        *(float4*)(As + n * 128 + (((2 * tm + 1) ^ xk) << 2)) = c1;
    }
    for (int i = tid * 4; i < 128 * 128; i += 1024)
        *(float4*)(Ws + i) = *(const float4*)(W2b + i);
    __syncthreads();

    #pragma unroll
    for (int i = 0; i < 8; i++)
        #pragma unroll
        for (int j = 0; j < 4; j++) accp[i][j] = 0ULL;

    gemm_tile(As, Ws, tm, tn, accp);

    float y[8][8];
    float b2v[8], gv[8], bev[8];
    #pragma unroll
    for (int j = 0; j < 8; j++) {
        int col = (j < 4) ? (4 * tn + j) : (64 + 4 * tn + j - 4);
        b2v[j] = b2b[col]; gv[j] = g2[col]; bev[j] = be2[col];
    }
    #pragma unroll
    for (int i = 0; i < 8; i++) {
        #pragma unroll
        for (int jp = 0; jp < 4; jp++)
            unpack2(accp[i][jp], y[i][2 * jp], y[i][2 * jp + 1]);
        float s = 0.f, s2 = 0.f;
        #pragma unroll
        for (int j = 0; j < 8; j++) {
            y[i][j] += b2v[j];
            s += y[i][j]; s2 += y[i][j] * y[i][j];
        }
        #pragma unroll
        for (int o = 1; o < 16; o <<= 1) {
            s  += __shfl_xor_sync(0xffffffffu, s, o);
            s2 += __shfl_xor_sync(0xffffffffu, s2, o);
        }
        float mean = s * (1.f / 128.f);
        float var  = s2 * (1.f / 128.f) - mean * mean;
        float rstd = rsqrtf(var + 1e-5f);
        int m = m0 + 8 * tm + i;
        if (m < NN) {
            float4 o0, o1;
            o0.x = (y[i][0] - mean) * rstd * gv[0] + bev[0];
            o0.y = (y[i][1] - mean) * rstd * gv[1] + bev[1];
            o0.z = (y[i][2] - mean) * rstd * gv[2] + bev[2];
            o0.w = (y[i][3] - mean) * rstd * gv[3] + bev[3];
            o1.x = (y[i][4] - mean) * rstd * gv[4] + bev[4];
            o1.y = (y[i][5] - mean) * rstd * gv[5] + bev[5];
            o1.z = (y[i][6] - mean) * rstd * gv[6] + bev[6];
            o1.w = (y[i][7] - mean) * rstd * gv[7] + bev[7];
            *(float4*)(out + (size_t)m * HH + 4 * tn) = o0;
            *(float4*)(out + (size_t)m * HH + 64 + 4 * tn) = o1;
        }
    }
}

extern "C" void kernel_launch(void* const* d_in, const int* in_sizes, int n_in,
                              void* d_out, int out_size) {
    const float* x         = (const float*)d_in[0];
    const void*  edge_idx  = d_in[1];
    const float* edge_attr = (const float*)d_in[2];
    const float* u         = (const float*)d_in[3];
    const float* W1a = (const float*)d_in[4];
    const float* b1a = (const float*)d_in[5];
    const float* W2a = (const float*)d_in[6];
    const float* b2a = (const float*)d_in[7];
    const float* g1  = (const float*)d_in[8];
    const float* be1 = (const float*)d_in[9];
    const float* W1b = (const float*)d_in[10];
    const float* b1b = (const float*)d_in[11];
    const float* W2b = (const float*)d_in[12];
    const float* b2b = (const float*)d_in[13];
    const float* g2  = (const float*)d_in[14];
    const float* be2 = (const float*)d_in[15];
    float* out = (float*)d_out;

    const int SM_PX   = (128 * 65 + 128 * 128) * 4;   //  98816 B
    const int SM_TILE = (128 * 128 * 2) * 4;          // 131072 B

    cudaFuncSetAttribute(px_kernel,   cudaFuncAttributeMaxDynamicSharedMemorySize, SM_PX);
    cudaFuncSetAttribute(edge_kernel, cudaFuncAttributeMaxDynamicSharedMemorySize, SM_TILE);
    cudaFuncSetAttribute(node_kernel, cudaFuncAttributeMaxDynamicSharedMemorySize, SM_TILE);

    detect_kernel<<<1, 32>>>((const int*)edge_idx);
    zero_kernel<<<2048, 256>>>();
    px_kernel<<<(NN + 63) / 64, 256, SM_PX>>>(x, W1a, b1a);
    edge_kernel<<<EE / 128, 256, SM_TILE>>>(edge_attr, edge_idx, W1a, W2a, b2a, g1, be1);
    node_kernel<<<(NN + 127) / 128, 256, SM_TILE>>>(x, u, W1b, b1b, W2b, b2b, g2, be2, out);
}

// round 8
// speedup vs baseline: 1.1751x; 1.1751x over previous
#include <cuda_runtime.h>

#define NN 50000
#define EE 800000
#define HH 128

// Scratch (device globals: no allocation allowed)
__device__ float g_summed[NN * HH];
__device__ float g_counts[NN];
__device__ float g_px[NN * HH];
__device__ int   g_idx64;

__device__ __forceinline__ int get_idx(const void* p, long long i) {
    return g_idx64 ? (int)((const long long*)p)[i] : ((const int*)p)[i];
}

// ---- packed f32x2 helpers (B300: FFMA-3reg is half-rate; f32x2 restores peak)
__device__ __forceinline__ unsigned long long pack2(float x, float y) {
    unsigned long long r;
    asm("mov.b64 %0, {%1, %2};" : "=l"(r) : "f"(x), "f"(y));
    return r;
}
__device__ __forceinline__ unsigned long long dup2(float x) {
    unsigned long long r;
    asm("mov.b64 %0, {%1, %1};" : "=l"(r) : "f"(x));
    return r;
}
__device__ __forceinline__ void unpack2(unsigned long long p, float& lo, float& hi) {
    asm("mov.b64 {%0, %1}, %2;" : "=f"(lo), "=f"(hi) : "l"(p));
}
__device__ __forceinline__ void ffma2(unsigned long long& d,
                                      unsigned long long a, unsigned long long b) {
    asm("fma.rn.f32x2 %0, %1, %2, %0;" : "+l"(d) : "l"(a), "l"(b));
}

// swizzled k-major tile addressing: 128 words per row, 4-float chunk XOR swizzle
__device__ __forceinline__ int tidx(int k, int m) {
    return k * 128 + ((((m >> 2) ^ ((k >> 2) & 31)) << 2) | (m & 3));
}

__global__ void detect_kernel(const int* __restrict__ idx32) {
    if (blockIdx.x == 0 && threadIdx.x == 0) {
        int is64 = 1;
        #pragma unroll 1
        for (int i = 0; i < 64; ++i) {
            if (idx32[2 * i + 1] != 0) { is64 = 0; break; }
        }
        g_idx64 = is64;
    }
}

__global__ void zero_kernel() {
    int stride = gridDim.x * blockDim.x;
    int t0 = blockIdx.x * blockDim.x + threadIdx.x;
    for (int j = t0; j < NN * HH; j += stride) g_summed[j] = 0.f;
    for (int j = t0; j < NN; j += stride) g_counts[j] = 0.f;
}

// 128x128x128 GEMM inner for 512 threads: 4x8 microtile.
// Thread (tm,tn), tm=0..31, tn=0..15: rows 4tm..4tm+3, cols {4tn..}+{64+4tn..}.
// As swizzled k-major, Ws plain row-major [k][n].
__device__ __forceinline__ void gemm4(const float* __restrict__ As,
                                      const float* __restrict__ Ws,
                                      int tm, int tn,
                                      unsigned long long accp[4][4]) {
    #pragma unroll 4
    for (int k = 0; k < 128; k++) {
        int xk = (k >> 2) & 31;
        float4 a0 = *(const float4*)(As + k * 128 + ((tm ^ xk) << 2));
        float4 b0 = *(const float4*)(Ws + k * 128 + 4 * tn);
        float4 b1 = *(const float4*)(Ws + k * 128 + 64 + 4 * tn);
        unsigned long long bp0 = pack2(b0.x, b0.y);
        unsigned long long bp1 = pack2(b0.z, b0.w);
        unsigned long long bp2 = pack2(b1.x, b1.y);
        unsigned long long bp3 = pack2(b1.z, b1.w);
        float a[4] = {a0.x, a0.y, a0.z, a0.w};
        #pragma unroll
        for (int i = 0; i < 4; i++) {
            unsigned long long ad = dup2(a[i]);
            ffma2(accp[i][0], ad, bp0);
            ffma2(accp[i][1], ad, bp1);
            ffma2(accp[i][2], ad, bp2);
            ffma2(accp[i][3], ad, bp3);
        }
    }
}

// ---------------------------------------------------------------------------
// px = x @ W1a[0:128,:] + b1a   (small share of runtime)
// ---------------------------------------------------------------------------
__global__ void px_kernel(const float* __restrict__ x,
                          const float* __restrict__ W1a,
                          const float* __restrict__ b1a) {
    extern __shared__ float sm[];
    float* As = sm;              // [128][65] k-major A tile
    float* Ws = sm + 128 * 65;   // [128][128]

    const int tid = threadIdx.x;
    const int tm = tid >> 4, tn = tid & 15;
    const int warp = tid >> 5, lane = tid & 31;
    const int m0 = blockIdx.x * 64;

    for (int r = warp; r < 64; r += 8) {
        int gm = m0 + r;
        float4 v = make_float4(0.f, 0.f, 0.f, 0.f);
        if (gm < NN) v = *(const float4*)(x + (size_t)gm * HH + lane * 4);
        int k = lane * 4;
        As[(k + 0) * 65 + r] = v.x;
        As[(k + 1) * 65 + r] = v.y;
        As[(k + 2) * 65 + r] = v.z;
        As[(k + 3) * 65 + r] = v.w;
    }
    for (int i = tid * 4; i < 128 * 128; i += 1024)
        *(float4*)(Ws + i) = *(const float4*)(W1a + i);
    __syncthreads();

    float acc[4][8];
    #pragma unroll
    for (int i = 0; i < 4; i++)
        #pragma unroll
        for (int j = 0; j < 8; j++) acc[i][j] = 0.f;

    #pragma unroll 4
    for (int k = 0; k < 128; k++) {
        float a[4], b[8];
        #pragma unroll
        for (int i = 0; i < 4; i++) a[i] = As[k * 65 + 4 * tm + i];
        float4 b0 = *(float4*)(Ws + k * 128 + 8 * tn);
        float4 b1 = *(float4*)(Ws + k * 128 + 8 * tn + 4);
        b[0] = b0.x; b[1] = b0.y; b[2] = b0.z; b[3] = b0.w;
        b[4] = b1.x; b[5] = b1.y; b[6] = b1.z; b[7] = b1.w;
        #pragma unroll
        for (int i = 0; i < 4; i++)
            #pragma unroll
            for (int j = 0; j < 8; j++) acc[i][j] += a[i] * b[j];
    }

    float bv[8];
    #pragma unroll
    for (int j = 0; j < 8; j++) bv[j] = b1a[8 * tn + j];
    #pragma unroll
    for (int i = 0; i < 4; i++) {
        int m = m0 + 4 * tm + i;
        if (m < NN) {
            float4 o0 = make_float4(acc[i][0] + bv[0], acc[i][1] + bv[1],
                                    acc[i][2] + bv[2], acc[i][3] + bv[3]);
            float4 o1 = make_float4(acc[i][4] + bv[4], acc[i][5] + bv[5],
                                    acc[i][6] + bv[6], acc[i][7] + bv[7]);
            *(float4*)(g_px + (size_t)m * HH + 8 * tn) = o0;
            *(float4*)(g_px + (size_t)m * HH + 8 * tn + 4) = o1;
        }
    }
}

// ---------------------------------------------------------------------------
// Edge kernel: 128-edge tiles, 512 threads, 4x8 microtile f32x2 GEMMs
// ---------------------------------------------------------------------------
__global__ __launch_bounds__(512, 1)
void edge_kernel(const float* __restrict__ edge_attr,
                 const void* __restrict__ eidx,
                 const float* __restrict__ W1a,
                 const float* __restrict__ W2a,
                 const float* __restrict__ b2a,
                 const float* __restrict__ g1,
                 const float* __restrict__ be1) {
    extern __shared__ float sm[];
    float* As = sm;              // swizzled k-major [128][128]
    float* Ws = sm + 128 * 128;  // [128][128]
    __shared__ int s_rows[128];
    __shared__ int s_cols[128];

    const int tid = threadIdx.x;
    const int tm = tid >> 4, tn = tid & 15;
    const int warp = tid >> 5, lane = tid & 31;
    const long long e0 = (long long)blockIdx.x * 128;

    if (tid < 128) {
        s_rows[tid] = get_idx(eidx, e0 + tid);
        s_cols[tid] = get_idx(eidx, (long long)EE + e0 + tid);
    }
    // edge_attr tile -> swizzled k-major
    for (int r = warp; r < 128; r += 16) {
        float4 v = *(const float4*)(edge_attr + (size_t)(e0 + r) * HH + 4 * lane);
        int k0 = 4 * lane;
        As[tidx(k0 + 0, r)] = v.x;
        As[tidx(k0 + 1, r)] = v.y;
        As[tidx(k0 + 2, r)] = v.z;
        As[tidx(k0 + 3, r)] = v.w;
    }
    const float* W1e = W1a + 128 * 128;
    for (int i = tid * 4; i < 128 * 128; i += 2048)
        *(float4*)(Ws + i) = *(const float4*)(W1e + i);
    __syncthreads();

    unsigned long long accp[4][4];
    #pragma unroll
    for (int i = 0; i < 4; i++)
        #pragma unroll
        for (int j = 0; j < 4; j++) accp[i][j] = 0ULL;

    gemm4(As, Ws, tm, tn, accp);

    // h = relu(acc + px[col])
    float h[4][8];
    #pragma unroll
    for (int i = 0; i < 4; i++) {
        #pragma unroll
        for (int jp = 0; jp < 4; jp++)
            unpack2(accp[i][jp], h[i][2 * jp], h[i][2 * jp + 1]);
        int c = s_cols[4 * tm + i];
        float4 p0 = *(const float4*)(g_px + (size_t)c * HH + 4 * tn);
        float4 p1 = *(const float4*)(g_px + (size_t)c * HH + 64 + 4 * tn);
        h[i][0] = fmaxf(h[i][0] + p0.x, 0.f);
        h[i][1] = fmaxf(h[i][1] + p0.y, 0.f);
        h[i][2] = fmaxf(h[i][2] + p0.z, 0.f);
        h[i][3] = fmaxf(h[i][3] + p0.w, 0.f);
        h[i][4] = fmaxf(h[i][4] + p1.x, 0.f);
        h[i][5] = fmaxf(h[i][5] + p1.y, 0.f);
        h[i][6] = fmaxf(h[i][6] + p1.z, 0.f);
        h[i][7] = fmaxf(h[i][7] + p1.w, 0.f);
    }
    __syncthreads();   // all GEMM1 reads of As/Ws complete

    // store h -> As (k-major over n), load W2a -> Ws
    #pragma unroll
    for (int j = 0; j < 8; j++) {
        int n = (j < 4) ? (4 * tn + j) : (64 + 4 * tn + j - 4);
        int xn = (n >> 2) & 31;
        float4 c0 = make_float4(h[0][j], h[1][j], h[2][j], h[3][j]);
        *(float4*)(As + n * 128 + ((tm ^ xn) << 2)) = c0;
    }
    for (int i = tid * 4; i < 128 * 128; i += 2048)
        *(float4*)(Ws + i) = *(const float4*)(W2a + i);
    __syncthreads();

    #pragma unroll
    for (int i = 0; i < 4; i++)
        #pragma unroll
        for (int j = 0; j < 4; j++) accp[i][j] = 0ULL;

    gemm4(As, Ws, tm, tn, accp);

    // epilogue: bias, LayerNorm per edge-row, atomic scatter
    float y[4][8];
    float b2v[8], gv[8], bev[8];
    #pragma unroll
    for (int j = 0; j < 8; j++) {
        int col = (j < 4) ? (4 * tn + j) : (64 + 4 * tn + j - 4);
        b2v[j] = b2a[col]; gv[j] = g1[col]; bev[j] = be1[col];
    }
    #pragma unroll
    for (int i = 0; i < 4; i++) {
        #pragma unroll
        for (int jp = 0; jp < 4; jp++)
            unpack2(accp[i][jp], y[i][2 * jp], y[i][2 * jp + 1]);
        float s = 0.f, s2 = 0.f;
        #pragma unroll
        for (int j = 0; j < 8; j++) {
            y[i][j] += b2v[j];
            s += y[i][j]; s2 += y[i][j] * y[i][j];
        }
        #pragma unroll
        for (int o = 1; o < 16; o <<= 1) {
            s  += __shfl_xor_sync(0xffffffffu, s, o);
            s2 += __shfl_xor_sync(0xffffffffu, s2, o);
        }
        float mean = s * (1.f / 128.f);
        float var  = s2 * (1.f / 128.f) - mean * mean;
        float rstd = rsqrtf(var + 1e-5f);
        int r = s_rows[4 * tm + i];
        float* dst = g_summed + (size_t)r * HH;
        #pragma unroll
        for (int j = 0; j < 8; j++) {
            int col = (j < 4) ? (4 * tn + j) : (64 + 4 * tn + j - 4);
            atomicAdd(dst + col, (y[i][j] - mean) * rstd * gv[j] + bev[j]);
        }
    }
    if (tn == 0) {
        #pragma unroll
        for (int i = 0; i < 4; i++)
            atomicAdd(&g_counts[s_rows[4 * tm + i]], 1.f);
    }
}

// ---------------------------------------------------------------------------
// Node kernel: z = [x, summed/max(cnt,1), u] (128x384), 512 threads
// ---------------------------------------------------------------------------
__global__ __launch_bounds__(512, 1)
void node_kernel(const float* __restrict__ x,
                 const float* __restrict__ u,
                 const float* __restrict__ W1b,
                 const float* __restrict__ b1b,
                 const float* __restrict__ W2b,
                 const float* __restrict__ b2b,
                 const float* __restrict__ g2,
                 const float* __restrict__ be2,
                 float* __restrict__ out) {
    extern __shared__ float sm[];
    float* As = sm;
    float* Ws = sm + 128 * 128;

    const int tid = threadIdx.x;
    const int tm = tid >> 4, tn = tid & 15;
    const int warp = tid >> 5, lane = tid & 31;
    const int m0 = blockIdx.x * 128;

    unsigned long long accp[4][4];
    #pragma unroll
    for (int i = 0; i < 4; i++)
        #pragma unroll
        for (int j = 0; j < 4; j++) accp[i][j] = 0ULL;

    for (int seg = 0; seg < 3; seg++) {
        if (seg) __syncthreads();  // prior GEMM reads done before overwrite
        for (int r = warp; r < 128; r += 16) {
            int gm = m0 + r;
            float4 v = make_float4(0.f, 0.f, 0.f, 0.f);
            if (gm < NN) {
                if (seg == 0) {
                    v = *(const float4*)(x + (size_t)gm * HH + 4 * lane);
                } else if (seg == 1) {
                    v = *(const float4*)(g_summed + (size_t)gm * HH + 4 * lane);
                    float inv = 1.f / fmaxf(g_counts[gm], 1.f);
                    v.x *= inv; v.y *= inv; v.z *= inv; v.w *= inv;
                } else {
                    v = *(const float4*)(u + (size_t)gm * HH + 4 * lane);
                }
            }
            int k0 = 4 * lane;
            As[tidx(k0 + 0, r)] = v.x;
            As[tidx(k0 + 1, r)] = v.y;
            As[tidx(k0 + 2, r)] = v.z;
            As[tidx(k0 + 3, r)] = v.w;
        }
        for (int i = tid * 4; i < 128 * 128; i += 2048)
            *(float4*)(Ws + i) = *(const float4*)(W1b + seg * 128 * 128 + i);
        __syncthreads();
        gemm4(As, Ws, tm, tn, accp);
    }

    // h = relu(acc + b1b)
    float h[4][8];
    float b1v[8];
    #pragma unroll
    for (int j = 0; j < 8; j++) {
        int col = (j < 4) ? (4 * tn + j) : (64 + 4 * tn + j - 4);
        b1v[j] = b1b[col];
    }
    #pragma unroll
    for (int i = 0; i < 4; i++) {
        #pragma unroll
        for (int jp = 0; jp < 4; jp++)
            unpack2(accp[i][jp], h[i][2 * jp], h[i][2 * jp + 1]);
        #pragma unroll
        for (int j = 0; j < 8; j++) h[i][j] = fmaxf(h[i][j] + b1v[j], 0.f);
    }
    __syncthreads();

    #pragma unroll
    for (int j = 0; j < 8; j++) {
        int n = (j < 4) ? (4 * tn + j) : (64 + 4 * tn + j - 4);
        int xn = (n >> 2) & 31;
        float4 c0 = make_float4(h[0][j], h[1][j], h[2][j], h[3][j]);
        *(float4*)(As + n * 128 + ((tm ^ xn) << 2)) = c0;
    }
    for (int i = tid * 4; i < 128 * 128; i += 2048)
        *(float4*)(Ws + i) = *(const float4*)(W2b + i);
    __syncthreads();

    #pragma unroll
    for (int i = 0; i < 4; i++)
        #pragma unroll
        for (int j = 0; j < 4; j++) accp[i][j] = 0ULL;

    gemm4(As, Ws, tm, tn, accp);

    float y[4][8];
    float b2v[8], gv[8], bev[8];
    #pragma unroll
    for (int j = 0; j < 8; j++) {
        int col = (j < 4) ? (4 * tn + j) : (64 + 4 * tn + j - 4);
        b2v[j] = b2b[col]; gv[j] = g2[col]; bev[j] = be2[col];
    }
    #pragma unroll
    for (int i = 0; i < 4; i++) {
        #pragma unroll
        for (int jp = 0; jp < 4; jp++)
            unpack2(accp[i][jp], y[i][2 * jp], y[i][2 * jp + 1]);
        float s = 0.f, s2 = 0.f;
        #pragma unroll
        for (int j = 0; j < 8; j++) {
            y[i][j] += b2v[j];
            s += y[i][j]; s2 += y[i][j] * y[i][j];
        }
        #pragma unroll
        for (int o = 1; o < 16; o <<= 1) {
            s  += __shfl_xor_sync(0xffffffffu, s, o);
            s2 += __shfl_xor_sync(0xffffffffu, s2, o);
        }
        float mean = s * (1.f / 128.f);
        float var  = s2 * (1.f / 128.f) - mean * mean;
        float rstd = rsqrtf(var + 1e-5f);
        int m = m0 + 4 * tm + i;
        if (m < NN) {
            float4 o0, o1;
            o0.x = (y[i][0] - mean) * rstd * gv[0] + bev[0];
            o0.y = (y[i][1] - mean) * rstd * gv[1] + bev[1];
            o0.z = (y[i][2] - mean) * rstd * gv[2] + bev[2];
            o0.w = (y[i][3] - mean) * rstd * gv[3] + bev[3];
            o1.x = (y[i][4] - mean) * rstd * gv[4] + bev[4];
            o1.y = (y[i][5] - mean) * rstd * gv[5] + bev[5];
            o1.z = (y[i][6] - mean) * rstd * gv[6] + bev[6];
            o1.w = (y[i][7] - mean) * rstd * gv[7] + bev[7];
            *(float4*)(out + (size_t)m * HH + 4 * tn) = o0;
            *(float4*)(out + (size_t)m * HH + 64 + 4 * tn) = o1;
        }
    }
}

extern "C" void kernel_launch(void* const* d_in, const int* in_sizes, int n_in,
                              void* d_out, int out_size) {
    const float* x         = (const float*)d_in[0];
    const void*  edge_idx  = d_in[1];
    const float* edge_attr = (const float*)d_in[2];
    const float* u         = (const float*)d_in[3];
    const float* W1a = (const float*)d_in[4];
    const float* b1a = (const float*)d_in[5];
    const float* W2a = (const float*)d_in[6];
    const float* b2a = (const float*)d_in[7];
    const float* g1  = (const float*)d_in[8];
    const float* be1 = (const float*)d_in[9];
    const float* W1b = (const float*)d_in[10];
    const float* b1b = (const float*)d_in[11];
    const float* W2b = (const float*)d_in[12];
    const float* b2b = (const float*)d_in[13];
    const float* g2  = (const float*)d_in[14];
    const float* be2 = (const float*)d_in[15];
    float* out = (float*)d_out;

    const int SM_PX   = (128 * 65 + 128 * 128) * 4;   //  98816 B
    const int SM_TILE = (128 * 128 * 2) * 4;          // 131072 B

    cudaFuncSetAttribute(px_kernel,   cudaFuncAttributeMaxDynamicSharedMemorySize, SM_PX);
    cudaFuncSetAttribute(edge_kernel, cudaFuncAttributeMaxDynamicSharedMemorySize, SM_TILE);
    cudaFuncSetAttribute(node_kernel, cudaFuncAttributeMaxDynamicSharedMemorySize, SM_TILE);

    detect_kernel<<<1, 32>>>((const int*)edge_idx);
    zero_kernel<<<2048, 256>>>();
    px_kernel<<<(NN + 63) / 64, 256, SM_PX>>>(x, W1a, b1a);
    edge_kernel<<<EE / 128, 512, SM_TILE>>>(edge_attr, edge_idx, W1a, W2a, b2a, g1, be1);
    node_kernel<<<(NN + 127) / 128, 512, SM_TILE>>>(x, u, W1b, b1b, W2b, b2b, g2, be2, out);
}